// round 15
// baseline (speedup 1.0000x reference)
#include <cuda_runtime.h>
#include <cuda_fp16.h>
#include <cstdint>
#include <math.h>

typedef __half f16;

// ===========================================================================
// TriParser, fp16 HMMA (f32 accum).
//   build_h16: h = [sentinel; x] -> hi|lo f16 [1024, 1024]
//   prep: U -> Up rows r=d*256+c, cols a f16 [65536,256]; W -> Wp split [256,1024]
//   proj (split 3-product HMMA): elu(h@W+b) -> f16 [1024,256]
//   per tri t:  stage1: t1[bi][d][c] = u @ Up^T
//               stage2: t2[bi][j][d] = v[b] @ t1[bi]^T
//               stage3: s[bi][j][k]  = t2[bi] @ w[b]^T  (f32 out)
// Per-tri s1->s2->s3 ordering for producer->consumer L2 locality
// (t1 slice 134MB ~ L2; t2 slice 67MB fits L2 fully).
// ===========================================================================

__device__ f16 g_h16[1024 * 1024];                     // 2 MB (hi|lo)
__device__ f16 g_Wp[7 * 256 * 1024];                   // 3.5 MB (hi|lo)
__device__ f16 g_projb[7 * 1024 * 256];                // 3.5 MB
__device__ f16 g_Up[3ull * 65536 * 256];               // 96 MB
__device__ f16 g_t1[1024ull * 65536];                  // 134 MB (one tri, reused)
__device__ f16 g_t2[1024ull * 32768];                  // 67 MB (one tri, reused)

static const size_t PB  = 1024 * 256;
static const size_t PBW = 256 * 1024;
static const size_t UPS = (size_t)65536 * 256;

__device__ __forceinline__ uint32_t smem_u32(const void* p) {
    uint32_t a;
    asm("{ .reg .u64 t; cvta.to.shared.u64 t, %1; cvt.u32.u64 %0, t; }"
        : "=r"(a) : "l"(p));
    return a;
}

#define SW128(o) ((o) ^ (((o) >> 3) & 0x70))

__device__ __forceinline__ void ldm_x4(uint32_t* r, uint32_t addr) {
    asm volatile("ldmatrix.sync.aligned.m8n8.x4.shared.b16 {%0,%1,%2,%3}, [%4];"
                 : "=r"(r[0]), "=r"(r[1]), "=r"(r[2]), "=r"(r[3]) : "r"(addr));
}

__device__ __forceinline__ void mma16816(float* c, const uint32_t* a, const uint32_t* b) {
    asm volatile(
        "mma.sync.aligned.m16n8k16.row.col.f32.f16.f16.f32 "
        "{%0,%1,%2,%3}, {%4,%5,%6,%7}, {%8,%9}, {%0,%1,%2,%3};"
        : "+f"(c[0]), "+f"(c[1]), "+f"(c[2]), "+f"(c[3])
        : "r"(a[0]), "r"(a[1]), "r"(a[2]), "r"(a[3]), "r"(b[0]), "r"(b[1]));
}

__device__ __forceinline__ void cpa16(uint32_t dst, const void* src) {
    asm volatile("cp.async.cg.shared.global [%0], [%1], 16;" :: "r"(dst), "l"(src) : "memory");
}
#define CP_COMMIT() asm volatile("cp.async.commit_group;" ::: "memory")
#define CP_WAIT1()  asm volatile("cp.async.wait_group 1;" ::: "memory")
#define CP_WAIT0()  asm volatile("cp.async.wait_group 0;" ::: "memory")

// PLAIN K64 tile, 128 rows (16KB), NT threads.
template <int NT>
__device__ __forceinline__ void load_plain(const f16* __restrict__ g, int rs, int c64,
                                           uint32_t dst, int tid) {
#pragma unroll
    for (int i = 0; i < 1024 / NT; i++) {
        int idx = tid + i * NT;
        int row = idx >> 3, seg = idx & 7;
        cpa16(dst + SW128(row * 128 + seg * 16), g + (size_t)row * rs + c64 * 64 + seg * 8);
    }
}

// SPLIT K32 tile (16KB): 128 rows x (hi 64B | lo 64B), NT threads.
template <int NT>
__device__ __forceinline__ void load_split(const f16* __restrict__ g, int rs, int loOff,
                                           int c32, uint32_t dst, int tid) {
#pragma unroll
    for (int i = 0; i < 1024 / NT; i++) {
        int idx = tid + i * NT;
        int row = idx >> 3, seg = idx & 7;
        int col = (seg < 4) ? c32 * 32 + seg * 8 : loOff + c32 * 32 + (seg - 4) * 8;
        cpa16(dst + SW128(row * 128 + seg * 16), g + (size_t)row * rs + col);
    }
}

// One K64 unit, 64x64 warp tile (MI=4): D[64 x 64] per warp.
__device__ __forceinline__ void mma_unit4(uint32_t ab, uint32_t bb,
                                          float (&acc)[4][8][4],
                                          int aLB, int bLB, int wm, int wn) {
#pragma unroll
    for (int kk = 0; kk < 4; kk++) {
        uint32_t aq[4][4], bq[4][4];
#pragma unroll
        for (int mi = 0; mi < 4; mi++) {
            int off = aLB + (wm * 64 + mi * 16) * 128 + kk * 32;
            ldm_x4(aq[mi], ab + SW128(off));
        }
#pragma unroll
        for (int nj = 0; nj < 4; nj++) {
            int off = bLB + (wn * 64 + nj * 16) * 128 + kk * 32;
            ldm_x4(bq[nj], bb + SW128(off));
        }
#pragma unroll
        for (int mi = 0; mi < 4; mi++)
#pragma unroll
            for (int nj = 0; nj < 4; nj++) {
                mma16816(acc[mi][nj * 2],     aq[mi], &bq[nj][0]);
                mma16816(acc[mi][nj * 2 + 1], aq[mi], &bq[nj][2]);
            }
    }
}

#define ZERO_ACC4(acc) \
    { _Pragma("unroll") for (int i = 0; i < 4; i++) \
      _Pragma("unroll") for (int j = 0; j < 8; j++) \
      _Pragma("unroll") for (int k = 0; k < 4; k++) acc[i][j][k] = 0.0f; }

#define WARP_IDS \
    const int tid = threadIdx.x; \
    const int lane = tid & 31; \
    const int warp = tid >> 5; \
    const int wm = warp >> 1, wn = warp & 1; \
    const int aLB = ((lane & 15) * 128) + ((lane >> 4) * 16); \
    const int bLB = (((lane & 7) + ((lane >> 4) << 3)) * 128) + (((lane >> 3) & 1) * 16); \
    const int gRow = lane >> 2; \
    const int cPair = (lane & 3) * 2;

// ===========================================================================
// Stage1 (one tri): t1 = u @ Up^T. grid (8 M, 64 Ngrp), 128 thr, 2 CTA/SM.
// ===========================================================================
__global__ __launch_bounds__(128, 2)
void stage1_k(const f16* __restrict__ U8, const f16* __restrict__ Ub,
              f16* __restrict__ T1t)
{
    extern __shared__ char dsm[];
    const uint32_t sraw = smem_u32(dsm);
    const uint32_t sb = (sraw + 1023u) & ~1023u;
    const uint32_t sbA = sb;
    const uint32_t sbB = sb + 65536;

    WARP_IDS

    const f16* Au = U8 + (size_t)blockIdx.x * 128 * 256;

    auto issueU = [&](int u) {
        if (u < 32) {
            int nt = u >> 2, ch = u & 3;
            load_plain<128>(Ub + ((size_t)blockIdx.y * 8 + nt) * 128 * 256, 256, ch,
                            sbB + (u & 1) * 16384, tid);
        }
        CP_COMMIT();
    };

#pragma unroll
    for (int ch = 0; ch < 4; ch++)
        load_plain<128>(Au, 256, ch, sbA + ch * 16384, tid);
    issueU(0);
    issueU(1);

    float acc[4][8][4];
    ZERO_ACC4(acc);

    for (int u = 0; u < 32; u++) {
        if (u < 31) CP_WAIT1(); else CP_WAIT0();
        __syncthreads();
        mma_unit4(sbA + (u & 3) * 16384, sbB + (u & 1) * 16384, acc, aLB, bLB, wm, wn);
        if (u < 30) { __syncthreads(); issueU(u + 2); }

        if ((u & 3) == 3) {
            int nt = u >> 2;
            size_t colBase = ((size_t)blockIdx.y * 8 + nt) * 128;
#pragma unroll
            for (int mi = 0; mi < 4; mi++) {
                int rbase = blockIdx.x * 128 + wm * 64 + mi * 16 + gRow;
#pragma unroll
                for (int f = 0; f < 8; f++) {
                    int nloc = wn * 64 + f * 8 + cPair;
#pragma unroll
                    for (int hh = 0; hh < 2; hh++) {
                        size_t row = (size_t)(rbase + hh * 8);
                        __half2 p;
                        p.x = __float2half(acc[mi][f][hh * 2 + 0]);
                        p.y = __float2half(acc[mi][f][hh * 2 + 1]);
                        *(__half2*)(T1t + row * 65536 + colBase + nloc) = p;
                        acc[mi][f][hh * 2 + 0] = 0.0f;
                        acc[mi][f][hh * 2 + 1] = 0.0f;
                    }
                }
            }
        }
    }
}

// ===========================================================================
// Stage2 (one tri): t2[tok][j][d] = v[b] @ t1[tok]^T. 2 tokens/CTA. grid 512.
// ===========================================================================
__global__ __launch_bounds__(128, 2)
void stage2_k(const f16* __restrict__ V, const f16* __restrict__ T1t,
              f16* __restrict__ T2t)
{
    extern __shared__ char dsm[];
    const uint32_t sraw = smem_u32(dsm);
    const uint32_t sb = (sraw + 1023u) & ~1023u;
    const uint32_t sbA = sb;
    const uint32_t sbB = sb + 65536;

    WARP_IDS

    const int z = blockIdx.x;
    const f16* Av = V + (size_t)(z >> 6) * 32768;

    auto issueU = [&](int g) {
        if (g < 16) {
            int tt = g >> 3, nh = (g >> 2) & 1, ch = g & 3;
            const f16* src = T1t + (size_t)(2 * z + tt) * 65536 + (size_t)nh * 128 * 256;
            load_plain<128>(src, 256, ch, sbB + (g & 1) * 16384, tid);
        }
        CP_COMMIT();
    };

#pragma unroll
    for (int ch = 0; ch < 4; ch++)
        load_plain<128>(Av, 256, ch, sbA + ch * 16384, tid);
    issueU(0);
    issueU(1);

    float acc[4][8][4];
    ZERO_ACC4(acc);

#pragma unroll
    for (int g = 0; g < 16; g++) {
        if (g < 15) CP_WAIT1(); else CP_WAIT0();
        __syncthreads();
        mma_unit4(sbA + (g & 3) * 16384, sbB + (g & 1) * 16384, acc, aLB, bLB, wm, wn);
        if (g < 14) { __syncthreads(); issueU(g + 2); }

        if ((g & 3) == 3) {
            int tt = g >> 3, nh = (g >> 2) & 1;
            f16* Cb = T2t + (size_t)(2 * z + tt) * 32768;
#pragma unroll
            for (int mi = 0; mi < 4; mi++) {
                int rbase = wm * 64 + mi * 16 + gRow;
#pragma unroll
                for (int f = 0; f < 8; f++) {
                    int col = nh * 128 + wn * 64 + f * 8 + cPair;
#pragma unroll
                    for (int hh = 0; hh < 2; hh++) {
                        size_t row = (size_t)(rbase + hh * 8);
                        __half2 p;
                        p.x = __float2half(acc[mi][f][hh * 2 + 0]);
                        p.y = __float2half(acc[mi][f][hh * 2 + 1]);
                        *(__half2*)(Cb + row * 256 + col) = p;
                        acc[mi][f][hh * 2 + 0] = 0.0f;
                        acc[mi][f][hh * 2 + 1] = 0.0f;
                    }
                }
            }
        }
    }
}

// ===========================================================================
// Stage3 (one tri): s[tok][j][k] = t2[tok] @ w[b]^T. 2 tokens/CTA. grid 512.
// ===========================================================================
__global__ __launch_bounds__(128, 2)
void stage3_k(const f16* __restrict__ W, const f16* __restrict__ T2t,
              float* __restrict__ Ot)
{
    extern __shared__ char dsm[];
    const uint32_t sraw = smem_u32(dsm);
    const uint32_t sb = (sraw + 1023u) & ~1023u;
    const uint32_t sbB = sb;          // resident w
    const uint32_t sbA = sb + 65536;  // streamed t2

    WARP_IDS

    const int z = blockIdx.x;
    const f16* Bw = W + (size_t)(z >> 6) * 32768;

    auto issueA = [&](int g) {
        if (g < 8) {
            int tt = g >> 2, ch = g & 3;
            load_plain<128>(T2t + (size_t)(2 * z + tt) * 32768, 256, ch,
                            sbA + (g & 1) * 16384, tid);
        }
        CP_COMMIT();
    };

#pragma unroll
    for (int ch = 0; ch < 4; ch++)
        load_plain<128>(Bw, 256, ch, sbB + ch * 16384, tid);
    issueA(0);
    issueA(1);

    float acc[4][8][4];
    ZERO_ACC4(acc);

#pragma unroll
    for (int g = 0; g < 8; g++) {
        if (g < 7) CP_WAIT1(); else CP_WAIT0();
        __syncthreads();
        mma_unit4(sbA + (g & 1) * 16384, sbB + (g & 3) * 16384, acc, aLB, bLB, wm, wn);
        if (g < 6) { __syncthreads(); issueA(g + 2); }

        if ((g & 3) == 3) {
            int tt = g >> 2;
            float* Cb = Ot + (size_t)(2 * z + tt) * 16384;
#pragma unroll
            for (int mi = 0; mi < 4; mi++) {
                int rbase = wm * 64 + mi * 16 + gRow;
#pragma unroll
                for (int f = 0; f < 8; f++) {
                    int col = wn * 64 + f * 8 + cPair;
#pragma unroll
                    for (int hh = 0; hh < 2; hh++) {
                        size_t row = (size_t)(rbase + hh * 8);
                        *(float2*)(Cb + row * 128 + col) =
                            make_float2(acc[mi][f][hh * 2 + 0], acc[mi][f][hh * 2 + 1]);
                        acc[mi][f][hh * 2 + 0] = 0.0f;
                        acc[mi][f][hh * 2 + 1] = 0.0f;
                    }
                }
            }
        }
    }
}

// ===========================================================================
// Projection, split 3-product HMMA: elu(h@W+b) -> f16 [1024,256]
// grid (8 M, 2 N, 7 branch), 256 thr. K=512 = 16 K32 steps, 2-deep.
// ===========================================================================
struct BiasArgs { const float* b[7]; };

__global__ __launch_bounds__(256, 2)
void proj_mma(BiasArgs ba, const f16* __restrict__ h16, const f16* __restrict__ Wp,
              f16* __restrict__ projb)
{
    extern __shared__ char dsm[];
    const uint32_t sraw = smem_u32(dsm);
    const uint32_t sb = (sraw + 1023u) & ~1023u;

    WARP_IDS

    const int br = blockIdx.z;
    const f16* A = h16 + (size_t)blockIdx.x * 128 * 1024;
    const f16* B = Wp + (size_t)br * PBW + (size_t)blockIdx.y * 128 * 1024;

    auto issue = [&](int s) {
        if (s < 16) {
            uint32_t buf = sb + (s & 1) * 32768;
            load_split<256>(A, 1024, 512, s, buf, tid);
            load_split<256>(B, 1024, 512, s, buf + 16384, tid);
        }
        CP_COMMIT();
    };
    issue(0); issue(1);

    float acc[2][8][4];
#pragma unroll
    for (int i = 0; i < 2; i++)
#pragma unroll
        for (int j = 0; j < 8; j++)
#pragma unroll
            for (int k = 0; k < 4; k++) acc[i][j][k] = 0.0f;

#pragma unroll
    for (int s = 0; s < 16; s++) {
        if (s < 15) CP_WAIT1(); else CP_WAIT0();
        __syncthreads();
        uint32_t ab = sb + (s & 1) * 32768;
        uint32_t bb = ab + 16384;
#pragma unroll
        for (int kk = 0; kk < 2; kk++) {
            uint32_t ah[2][4], al[2][4], bh[4][4], bl[4][4];
#pragma unroll
            for (int mi = 0; mi < 2; mi++) {
                int off = aLB + (wm * 32 + mi * 16) * 128 + kk * 32;
                ldm_x4(ah[mi], ab + SW128(off));
                ldm_x4(al[mi], ab + SW128(off + 64));
            }
#pragma unroll
            for (int nj = 0; nj < 4; nj++) {
                int off = bLB + (wn * 64 + nj * 16) * 128 + kk * 32;
                ldm_x4(bh[nj], bb + SW128(off));
                ldm_x4(bl[nj], bb + SW128(off + 64));
            }
#pragma unroll
            for (int mi = 0; mi < 2; mi++)
#pragma unroll
                for (int nj = 0; nj < 4; nj++) {
                    mma16816(acc[mi][nj * 2],     ah[mi], &bh[nj][0]);
                    mma16816(acc[mi][nj * 2 + 1], ah[mi], &bh[nj][2]);
                    mma16816(acc[mi][nj * 2],     ah[mi], &bl[nj][0]);
                    mma16816(acc[mi][nj * 2 + 1], ah[mi], &bl[nj][2]);
                    mma16816(acc[mi][nj * 2],     al[mi], &bh[nj][0]);
                    mma16816(acc[mi][nj * 2 + 1], al[mi], &bh[nj][2]);
                }
        }
        if (s < 14) { __syncthreads(); issue(s + 2); }
    }

    const float* bias = ba.b[br];
    f16* Co = projb + (size_t)br * PB;
#pragma unroll
    for (int mi = 0; mi < 2; mi++) {
        int rbase = blockIdx.x * 128 + wm * 32 + mi * 16 + gRow;
#pragma unroll
        for (int f = 0; f < 8; f++) {
            int col = blockIdx.y * 128 + wn * 64 + f * 8 + cPair;
#pragma unroll
            for (int hh = 0; hh < 2; hh++) {
                int row = rbase + hh * 8;
                float v0 = acc[mi][f][hh * 2 + 0] + bias[col];
                float v1 = acc[mi][f][hh * 2 + 1] + bias[col + 1];
                v0 = v0 > 0.f ? v0 : expm1f(v0);
                v1 = v1 > 0.f ? v1 : expm1f(v1);
                __half2 p;
                p.x = __float2half(v0);
                p.y = __float2half(v1);
                *(__half2*)(Co + (size_t)row * 256 + col) = p;
            }
        }
    }
}

// ===========================================================================
// Prep kernel: z < 768 -> Up permute; z >= 768 -> W transpose+split.
// ===========================================================================
struct PtrU { const float* p[3]; };
struct PtrW { const float* p[7]; };

__global__ void prep_k(PtrU Us, f16* __restrict__ Up, PtrW Ws, f16* __restrict__ Wp)
{
    __shared__ float t[32][33];
    const int zz = blockIdx.z;
    const int tx = threadIdx.x;
    const int ty = threadIdx.y;

    if (zz < 768) {
        const int tri = zz >> 8;
        const int c = zz & 255;
        const float* U = Us.p[tri];
        f16* Upt = Up + (size_t)tri * UPS;
        const int d0 = blockIdx.x * 32;
        const int a0 = blockIdx.y * 32;
#pragma unroll
        for (int i = 0; i < 32; i += 8)
            t[ty + i][tx] = U[(size_t)(a0 + ty + i) * 65536 + c * 256 + d0 + tx];
        __syncthreads();
#pragma unroll
        for (int i = 0; i < 32; i += 8) {
            int dl = ty + i;
            size_t rowbase = ((size_t)(d0 + dl) * 256 + c) * 256;
            Upt[rowbase + a0 + tx] = __float2half(t[tx][dl]);
        }
    } else {
        const int br = zz - 768;
        const float* W = Ws.p[br];
        f16* Wpt = Wp + (size_t)br * PBW;
        for (int t2i = 0; t2i < 2; t2i++) {
            int tile = ((blockIdx.y * 8 + blockIdx.x) * 2 + t2i);
            int k0 = (tile >> 3) * 32;
            int n0 = (tile & 7) * 32;
            __syncthreads();
#pragma unroll
            for (int i = 0; i < 32; i += 8)
                t[ty + i][tx] = W[(size_t)(k0 + ty + i) * 256 + n0 + tx];
            __syncthreads();
#pragma unroll
            for (int i = 0; i < 32; i += 8) {
                int dl = ty + i;
                float v = t[tx][dl];
                f16 hb = __float2half(v);
                f16 lb = __float2half(v - __half2float(hb));
                size_t rowbase = (size_t)(n0 + dl) * 1024;
                Wpt[rowbase + k0 + tx] = hb;
                Wpt[rowbase + 512 + k0 + tx] = lb;
            }
        }
    }
}

__global__ void build_h16(const float* __restrict__ x, const float* __restrict__ sent,
                          f16* __restrict__ h16)
{
    int idx = blockIdx.x * blockDim.x + threadIdx.x;   // 1024*512
    int rowi = idx >> 9;
    int e = idx & 511;
    int t = rowi & 127;
    int b = rowi >> 7;
    float v = (t == 0) ? sent[e] : x[((size_t)(b * 127 + t - 1)) * 512 + e];
    f16 hb = __float2half(v);
    f16 lb = __float2half(v - __half2float(hb));
    h16[(size_t)rowi * 1024 + e] = hb;
    h16[(size_t)rowi * 1024 + 512 + e] = lb;
}

__global__ void write_mask(const int* __restrict__ mask, float* __restrict__ outm)
{
    int i = blockIdx.x * blockDim.x + threadIdx.x;
    if (i < 1024) {
        int b = i >> 7, t = i & 127;
        outm[i] = (t == 0) ? 1.0f : (float)mask[b * 127 + t - 1];
    }
}

// ===========================================================================
extern "C" void kernel_launch(void* const* d_in, const int* in_sizes, int n_in,
                              void* d_out, int out_size)
{
    (void)in_sizes; (void)n_in; (void)out_size;

    const float* x    = (const float*)d_in[0];
    const int*   mask = (const int*)d_in[2];
    const float* sent = (const float*)d_in[20];
    float* out = (float*)d_out;

    f16 *h16, *Wpb, *projb, *Up, *t1, *t2;
    cudaGetSymbolAddress((void**)&h16,   g_h16);
    cudaGetSymbolAddress((void**)&Wpb,   g_Wp);
    cudaGetSymbolAddress((void**)&projb, g_projb);
    cudaGetSymbolAddress((void**)&Up,    g_Up);
    cudaGetSymbolAddress((void**)&t1,    g_t1);
    cudaGetSymbolAddress((void**)&t2,    g_t2);

    const int SMEM  = 65536 + 2 * 16384 + 1024;   // 99328 -> 2 CTAs/SM
    const int SMEMP = 2 * 32768 + 1024;           // 66560 -> 2 CTAs/SM
    cudaFuncSetAttribute(stage1_k, cudaFuncAttributeMaxDynamicSharedMemorySize, SMEM);
    cudaFuncSetAttribute(stage2_k, cudaFuncAttributeMaxDynamicSharedMemorySize, SMEM);
    cudaFuncSetAttribute(stage3_k, cudaFuncAttributeMaxDynamicSharedMemorySize, SMEM);
    cudaFuncSetAttribute(proj_mma, cudaFuncAttributeMaxDynamicSharedMemorySize, SMEMP);

    BiasArgs ba;
    PtrW ws;
    for (int i = 0; i < 7; i++) {
        ws.p[i] = (const float*)d_in[3 + 2 * i];
        ba.b[i] = (const float*)d_in[4 + 2 * i];
    }
    PtrU us;
    us.p[0] = (const float*)d_in[17];
    us.p[1] = (const float*)d_in[18];
    us.p[2] = (const float*)d_in[19];

    // branches: 0 sib_head, 1 sib_dep, 2 cop_head, 3 cop_dep,
    //           4 gp_head, 5 gp_dep, 6 gp_head_dep
    const int ui[3] = {0, 2, 4};
    const int vi[3] = {1, 3, 6};
    const int wi[3] = {1, 2, 5};

    build_h16<<<2048, 256>>>(x, sent, h16);                          // 0
    prep_k<<<dim3(8, 8, 775), dim3(32, 8)>>>(us, Up, ws, Wpb);       // 1
    proj_mma<<<dim3(8, 2, 7), 256, SMEMP>>>(ba, h16, Wpb, projb);    // 2

    for (int t = 0; t < 3; t++) {
        // producer->consumer per tri: t1 (134MB ~ L2), t2 (67MB, fits L2)
        stage1_k<<<dim3(8, 64), 128, SMEM>>>(                        // slot 3 = t=0
            projb + ui[t] * PB, Up + (size_t)t * UPS, t1);
        stage2_k<<<512, 128, SMEM>>>(projb + vi[t] * PB, t1, t2);
        stage3_k<<<512, 128, SMEM>>>(projb + wi[t] * PB, t2,
                                     out + (size_t)t * 16777216);
    }

    write_mask<<<4, 256>>>(mask, out + (size_t)3 * 16777216);
}

// round 16
// speedup vs baseline: 1.1140x; 1.1140x over previous
#include <cuda_runtime.h>
#include <cuda_fp16.h>
#include <cstdint>
#include <math.h>

typedef __half f16;

// ===========================================================================
// TriParser, fp16 HMMA (f32 accum).
//   build_h16: h = [sentinel; x] -> hi|lo f16 [1024, 1024]
//   prep: U -> Up rows r=d*256+c, cols a f16 [65536,256]; W -> Wp split [256,1024]
//   proj (split 3-product HMMA): elu(h@W+b) -> f16 [1024,256]
//   stage1: t1[bi][d][c] = u @ Up^T
//   stage2: t2[bi][j][d] = v[b] @ t1[bi]^T
//   stage3: s[bi][j][k]  = t2[bi] @ w[b]^T  (f32 out)
// Merged per-stage launches (all tris). Stage kernels: 128 thr, 64x64 warp
// tiles, 3-deep cp.async ring, ONE __syncthreads per K64 unit, 2 CTA/SM.
// ===========================================================================

__device__ f16 g_h16[1024 * 1024];                     // 2 MB (hi|lo)
__device__ f16 g_Wp[7 * 256 * 1024];                   // 3.5 MB (hi|lo)
__device__ f16 g_projb[7 * 1024 * 256];                // 3.5 MB
__device__ f16 g_Up[3ull * 65536 * 256];               // 96 MB
__device__ f16 g_t1[3ull * 1024 * 65536];              // 402 MB
__device__ f16 g_t2[3ull * 1024 * 128 * 256];          // 201 MB

static const size_t PB  = 1024 * 256;
static const size_t PBW = 256 * 1024;
static const size_t UPS = (size_t)65536 * 256;
static const size_t T1S = (size_t)1024 * 65536;
static const size_t T2S = (size_t)1024 * 32768;

__device__ __forceinline__ uint32_t smem_u32(const void* p) {
    uint32_t a;
    asm("{ .reg .u64 t; cvta.to.shared.u64 t, %1; cvt.u32.u64 %0, t; }"
        : "=r"(a) : "l"(p));
    return a;
}

#define SW128(o) ((o) ^ (((o) >> 3) & 0x70))

__device__ __forceinline__ void ldm_x4(uint32_t* r, uint32_t addr) {
    asm volatile("ldmatrix.sync.aligned.m8n8.x4.shared.b16 {%0,%1,%2,%3}, [%4];"
                 : "=r"(r[0]), "=r"(r[1]), "=r"(r[2]), "=r"(r[3]) : "r"(addr));
}

__device__ __forceinline__ void mma16816(float* c, const uint32_t* a, const uint32_t* b) {
    asm volatile(
        "mma.sync.aligned.m16n8k16.row.col.f32.f16.f16.f32 "
        "{%0,%1,%2,%3}, {%4,%5,%6,%7}, {%8,%9}, {%0,%1,%2,%3};"
        : "+f"(c[0]), "+f"(c[1]), "+f"(c[2]), "+f"(c[3])
        : "r"(a[0]), "r"(a[1]), "r"(a[2]), "r"(a[3]), "r"(b[0]), "r"(b[1]));
}

__device__ __forceinline__ void cpa16(uint32_t dst, const void* src) {
    asm volatile("cp.async.cg.shared.global [%0], [%1], 16;" :: "r"(dst), "l"(src) : "memory");
}
#define CP_COMMIT() asm volatile("cp.async.commit_group;" ::: "memory")
#define CP_WAIT1()  asm volatile("cp.async.wait_group 1;" ::: "memory")
#define CP_WAIT0()  asm volatile("cp.async.wait_group 0;" ::: "memory")

// PLAIN K64 tile, 128 rows (16KB), NT threads.
template <int NT>
__device__ __forceinline__ void load_plain(const f16* __restrict__ g, int rs, int c64,
                                           uint32_t dst, int tid) {
#pragma unroll
    for (int i = 0; i < 1024 / NT; i++) {
        int idx = tid + i * NT;
        int row = idx >> 3, seg = idx & 7;
        cpa16(dst + SW128(row * 128 + seg * 16), g + (size_t)row * rs + c64 * 64 + seg * 8);
    }
}

// SPLIT K32 tile (16KB): 128 rows x (hi 64B | lo 64B), NT threads.
template <int NT>
__device__ __forceinline__ void load_split(const f16* __restrict__ g, int rs, int loOff,
                                           int c32, uint32_t dst, int tid) {
#pragma unroll
    for (int i = 0; i < 1024 / NT; i++) {
        int idx = tid + i * NT;
        int row = idx >> 3, seg = idx & 7;
        int col = (seg < 4) ? c32 * 32 + seg * 8 : loOff + c32 * 32 + (seg - 4) * 8;
        cpa16(dst + SW128(row * 128 + seg * 16), g + (size_t)row * rs + col);
    }
}

// One K64 unit, 64x64 warp tile (MI=4): D[64 x 64] per warp.
__device__ __forceinline__ void mma_unit4(uint32_t ab, uint32_t bb,
                                          float (&acc)[4][8][4],
                                          int aLB, int bLB, int wm, int wn) {
#pragma unroll
    for (int kk = 0; kk < 4; kk++) {
        uint32_t aq[4][4], bq[4][4];
#pragma unroll
        for (int mi = 0; mi < 4; mi++) {
            int off = aLB + (wm * 64 + mi * 16) * 128 + kk * 32;
            ldm_x4(aq[mi], ab + SW128(off));
        }
#pragma unroll
        for (int nj = 0; nj < 4; nj++) {
            int off = bLB + (wn * 64 + nj * 16) * 128 + kk * 32;
            ldm_x4(bq[nj], bb + SW128(off));
        }
#pragma unroll
        for (int mi = 0; mi < 4; mi++)
#pragma unroll
            for (int nj = 0; nj < 4; nj++) {
                mma16816(acc[mi][nj * 2],     aq[mi], &bq[nj][0]);
                mma16816(acc[mi][nj * 2 + 1], aq[mi], &bq[nj][2]);
            }
    }
}

#define ZERO_ACC4(acc) \
    { _Pragma("unroll") for (int i = 0; i < 4; i++) \
      _Pragma("unroll") for (int j = 0; j < 8; j++) \
      _Pragma("unroll") for (int k = 0; k < 4; k++) acc[i][j][k] = 0.0f; }

#define WARP_IDS \
    const int tid = threadIdx.x; \
    const int lane = tid & 31; \
    const int warp = tid >> 5; \
    const int wm = warp >> 1, wn = warp & 1; \
    const int aLB = ((lane & 15) * 128) + ((lane >> 4) * 16); \
    const int bLB = (((lane & 7) + ((lane >> 4) << 3)) * 128) + (((lane >> 3) & 1) * 16); \
    const int gRow = lane >> 2; \
    const int cPair = (lane & 3) * 2;

// ===========================================================================
// Stage1 (all tris): t1 = u @ Up^T. grid (8 M, 64 Ngrp, 3 tri), 128 thr.
// A [128x256] resident (64KB); B ring 3x16KB; 1 sync per K64 unit.
// ===========================================================================
__global__ __launch_bounds__(128, 2)
void stage1_k(const f16* __restrict__ projb, const f16* __restrict__ Up,
              f16* __restrict__ T1)
{
    extern __shared__ char dsm[];
    const uint32_t sraw = smem_u32(dsm);
    const uint32_t sb = (sraw + 1023u) & ~1023u;
    const uint32_t sbA = sb;
    const uint32_t sbB = sb + 65536;

    WARP_IDS

    const int tri = blockIdx.z;
    const f16* Au = projb + (size_t)(2 * tri) * PB + (size_t)blockIdx.x * 128 * 256;
    const f16* Ub = Up + (size_t)tri * UPS;
    f16* T1t = T1 + (size_t)tri * T1S;

    auto issueU = [&](int u) {
        if (u < 32) {
            int nt = u >> 2, ch = u & 3;
            load_plain<128>(Ub + ((size_t)blockIdx.y * 8 + nt) * 128 * 256, 256, ch,
                            sbB + (u % 3) * 16384, tid);
        }
        CP_COMMIT();
    };

#pragma unroll
    for (int ch = 0; ch < 4; ch++)
        load_plain<128>(Au, 256, ch, sbA + ch * 16384, tid);
    issueU(0);   // commit covers resident A + B tile 0
    issueU(1);

    float acc[4][8][4];
    ZERO_ACC4(acc);

    for (int u = 0; u < 32; u++) {
        if (u < 31) CP_WAIT1(); else CP_WAIT0();
        __syncthreads();                      // buf u ready; unit u-1 consumers done
        issueU(u + 2);                        // writes buf (u+2)%3 == buf (u-1)%3
        mma_unit4(sbA + (u & 3) * 16384, sbB + (u % 3) * 16384, acc, aLB, bLB, wm, wn);

        if ((u & 3) == 3) {
            int nt = u >> 2;
            size_t colBase = ((size_t)blockIdx.y * 8 + nt) * 128;
#pragma unroll
            for (int mi = 0; mi < 4; mi++) {
                int rbase = blockIdx.x * 128 + wm * 64 + mi * 16 + gRow;
#pragma unroll
                for (int f = 0; f < 8; f++) {
                    int nloc = wn * 64 + f * 8 + cPair;
#pragma unroll
                    for (int hh = 0; hh < 2; hh++) {
                        size_t row = (size_t)(rbase + hh * 8);
                        __half2 p;
                        p.x = __float2half(acc[mi][f][hh * 2 + 0]);
                        p.y = __float2half(acc[mi][f][hh * 2 + 1]);
                        *(__half2*)(T1t + row * 65536 + colBase + nloc) = p;
                        acc[mi][f][hh * 2 + 0] = 0.0f;
                        acc[mi][f][hh * 2 + 1] = 0.0f;
                    }
                }
            }
        }
    }
}

// ===========================================================================
// Stage2 (all tris): t2[tok][j][d] = v[b] @ t1[tok]^T. 2 tokens/CTA.
// grid (512, 3), 128 thr. v resident; t1 ring 3x16KB, 1 sync/unit.
// ===========================================================================
struct Ptr3 { const f16* p[3]; };

__global__ __launch_bounds__(128, 2)
void stage2_k(Ptr3 vp, const f16* __restrict__ T1, f16* __restrict__ T2)
{
    extern __shared__ char dsm[];
    const uint32_t sraw = smem_u32(dsm);
    const uint32_t sb = (sraw + 1023u) & ~1023u;
    const uint32_t sbA = sb;
    const uint32_t sbB = sb + 65536;

    WARP_IDS

    const int z = blockIdx.x;
    const int tri = blockIdx.y;
    const f16* Av = vp.p[tri] + (size_t)(z >> 6) * 32768;
    const f16* T1t = T1 + (size_t)tri * T1S;
    f16* T2t = T2 + (size_t)tri * T2S;

    auto issueU = [&](int g) {
        if (g < 16) {
            int tt = g >> 3, nh = (g >> 2) & 1, ch = g & 3;
            const f16* src = T1t + (size_t)(2 * z + tt) * 65536 + (size_t)nh * 128 * 256;
            load_plain<128>(src, 256, ch, sbB + (g % 3) * 16384, tid);
        }
        CP_COMMIT();
    };

#pragma unroll
    for (int ch = 0; ch < 4; ch++)
        load_plain<128>(Av, 256, ch, sbA + ch * 16384, tid);
    issueU(0);
    issueU(1);

    float acc[4][8][4];
    ZERO_ACC4(acc);

#pragma unroll
    for (int g = 0; g < 16; g++) {
        if (g < 15) CP_WAIT1(); else CP_WAIT0();
        __syncthreads();
        issueU(g + 2);
        mma_unit4(sbA + (g & 3) * 16384, sbB + (g % 3) * 16384, acc, aLB, bLB, wm, wn);

        if ((g & 3) == 3) {
            int tt = g >> 3, nh = (g >> 2) & 1;
            f16* Cb = T2t + (size_t)(2 * z + tt) * 32768;
#pragma unroll
            for (int mi = 0; mi < 4; mi++) {
                int rbase = wm * 64 + mi * 16 + gRow;
#pragma unroll
                for (int f = 0; f < 8; f++) {
                    int col = nh * 128 + wn * 64 + f * 8 + cPair;
#pragma unroll
                    for (int hh = 0; hh < 2; hh++) {
                        size_t row = (size_t)(rbase + hh * 8);
                        __half2 p;
                        p.x = __float2half(acc[mi][f][hh * 2 + 0]);
                        p.y = __float2half(acc[mi][f][hh * 2 + 1]);
                        *(__half2*)(Cb + row * 256 + col) = p;
                        acc[mi][f][hh * 2 + 0] = 0.0f;
                        acc[mi][f][hh * 2 + 1] = 0.0f;
                    }
                }
            }
        }
    }
}

// ===========================================================================
// Stage3 (all tris): s[tok][j][k] = t2[tok] @ w[b]^T. 2 tokens/CTA.
// grid (512, 3), 128 thr. w resident as B; t2 ring 3x16KB as A. f32 out.
// ===========================================================================
__global__ __launch_bounds__(128, 2)
void stage3_k(Ptr3 wp, const f16* __restrict__ T2, float* __restrict__ OUT)
{
    extern __shared__ char dsm[];
    const uint32_t sraw = smem_u32(dsm);
    const uint32_t sb = (sraw + 1023u) & ~1023u;
    const uint32_t sbB = sb;          // resident w
    const uint32_t sbA = sb + 65536;  // streamed t2 ring

    WARP_IDS

    const int z = blockIdx.x;
    const int tri = blockIdx.y;
    const f16* Bw = wp.p[tri] + (size_t)(z >> 6) * 32768;
    const f16* T2t = T2 + (size_t)tri * T2S;
    float* Ot = OUT + (size_t)tri * 16777216;

    auto issueA = [&](int g) {
        if (g < 8) {
            int tt = g >> 2, ch = g & 3;
            load_plain<128>(T2t + (size_t)(2 * z + tt) * 32768, 256, ch,
                            sbA + (g % 3) * 16384, tid);
        }
        CP_COMMIT();
    };

#pragma unroll
    for (int ch = 0; ch < 4; ch++)
        load_plain<128>(Bw, 256, ch, sbB + ch * 16384, tid);
    issueA(0);
    issueA(1);

    float acc[4][8][4];
    ZERO_ACC4(acc);

#pragma unroll
    for (int g = 0; g < 8; g++) {
        if (g < 7) CP_WAIT1(); else CP_WAIT0();
        __syncthreads();
        issueA(g + 2);
        mma_unit4(sbA + (g % 3) * 16384, sbB + (g & 3) * 16384, acc, aLB, bLB, wm, wn);

        if ((g & 3) == 3) {
            int tt = g >> 2;
            float* Cb = Ot + (size_t)(2 * z + tt) * 16384;
#pragma unroll
            for (int mi = 0; mi < 4; mi++) {
                int rbase = wm * 64 + mi * 16 + gRow;
#pragma unroll
                for (int f = 0; f < 8; f++) {
                    int col = wn * 64 + f * 8 + cPair;
#pragma unroll
                    for (int hh = 0; hh < 2; hh++) {
                        size_t row = (size_t)(rbase + hh * 8);
                        *(float2*)(Cb + row * 128 + col) =
                            make_float2(acc[mi][f][hh * 2 + 0], acc[mi][f][hh * 2 + 1]);
                        acc[mi][f][hh * 2 + 0] = 0.0f;
                        acc[mi][f][hh * 2 + 1] = 0.0f;
                    }
                }
            }
        }
    }
}

// ===========================================================================
// Projection, split 3-product HMMA: elu(h@W+b) -> f16 [1024,256]
// grid (8 M, 2 N, 7 branch), 256 thr. K=512 = 16 K32 steps, 2-deep.
// ===========================================================================
struct BiasArgs { const float* b[7]; };

__global__ __launch_bounds__(256, 2)
void proj_mma(BiasArgs ba, const f16* __restrict__ h16, const f16* __restrict__ Wp,
              f16* __restrict__ projb)
{
    extern __shared__ char dsm[];
    const uint32_t sraw = smem_u32(dsm);
    const uint32_t sb = (sraw + 1023u) & ~1023u;

    WARP_IDS

    const int br = blockIdx.z;
    const f16* A = h16 + (size_t)blockIdx.x * 128 * 1024;
    const f16* B = Wp + (size_t)br * PBW + (size_t)blockIdx.y * 128 * 1024;

    auto issue = [&](int s) {
        if (s < 16) {
            uint32_t buf = sb + (s & 1) * 32768;
            load_split<256>(A, 1024, 512, s, buf, tid);
            load_split<256>(B, 1024, 512, s, buf + 16384, tid);
        }
        CP_COMMIT();
    };
    issue(0); issue(1);

    float acc[2][8][4];
#pragma unroll
    for (int i = 0; i < 2; i++)
#pragma unroll
        for (int j = 0; j < 8; j++)
#pragma unroll
            for (int k = 0; k < 4; k++) acc[i][j][k] = 0.0f;

#pragma unroll
    for (int s = 0; s < 16; s++) {
        if (s < 15) CP_WAIT1(); else CP_WAIT0();
        __syncthreads();
        uint32_t ab = sb + (s & 1) * 32768;
        uint32_t bb = ab + 16384;
#pragma unroll
        for (int kk = 0; kk < 2; kk++) {
            uint32_t ah[2][4], al[2][4], bh[4][4], bl[4][4];
#pragma unroll
            for (int mi = 0; mi < 2; mi++) {
                int off = aLB + (wm * 32 + mi * 16) * 128 + kk * 32;
                ldm_x4(ah[mi], ab + SW128(off));
                ldm_x4(al[mi], ab + SW128(off + 64));
            }
#pragma unroll
            for (int nj = 0; nj < 4; nj++) {
                int off = bLB + (wn * 64 + nj * 16) * 128 + kk * 32;
                ldm_x4(bh[nj], bb + SW128(off));
                ldm_x4(bl[nj], bb + SW128(off + 64));
            }
#pragma unroll
            for (int mi = 0; mi < 2; mi++)
#pragma unroll
                for (int nj = 0; nj < 4; nj++) {
                    mma16816(acc[mi][nj * 2],     ah[mi], &bh[nj][0]);
                    mma16816(acc[mi][nj * 2 + 1], ah[mi], &bh[nj][2]);
                    mma16816(acc[mi][nj * 2],     ah[mi], &bl[nj][0]);
                    mma16816(acc[mi][nj * 2 + 1], ah[mi], &bl[nj][2]);
                    mma16816(acc[mi][nj * 2],     al[mi], &bh[nj][0]);
                    mma16816(acc[mi][nj * 2 + 1], al[mi], &bh[nj][2]);
                }
        }
        if (s < 14) { __syncthreads(); issue(s + 2); }
    }

    const float* bias = ba.b[br];
    f16* Co = projb + (size_t)br * PB;
#pragma unroll
    for (int mi = 0; mi < 2; mi++) {
        int rbase = blockIdx.x * 128 + wm * 32 + mi * 16 + gRow;
#pragma unroll
        for (int f = 0; f < 8; f++) {
            int col = blockIdx.y * 128 + wn * 64 + f * 8 + cPair;
#pragma unroll
            for (int hh = 0; hh < 2; hh++) {
                int row = rbase + hh * 8;
                float v0 = acc[mi][f][hh * 2 + 0] + bias[col];
                float v1 = acc[mi][f][hh * 2 + 1] + bias[col + 1];
                v0 = v0 > 0.f ? v0 : expm1f(v0);
                v1 = v1 > 0.f ? v1 : expm1f(v1);
                __half2 p;
                p.x = __float2half(v0);
                p.y = __float2half(v1);
                *(__half2*)(Co + (size_t)row * 256 + col) = p;
            }
        }
    }
}

// ===========================================================================
// Prep kernel: z < 768 -> Up permute; z >= 768 -> W transpose+split.
// ===========================================================================
struct PtrU { const float* p[3]; };
struct PtrW { const float* p[7]; };

__global__ void prep_k(PtrU Us, f16* __restrict__ Up, PtrW Ws, f16* __restrict__ Wp)
{
    __shared__ float t[32][33];
    const int zz = blockIdx.z;
    const int tx = threadIdx.x;
    const int ty = threadIdx.y;

    if (zz < 768) {
        const int tri = zz >> 8;
        const int c = zz & 255;
        const float* U = Us.p[tri];
        f16* Upt = Up + (size_t)tri * UPS;
        const int d0 = blockIdx.x * 32;
        const int a0 = blockIdx.y * 32;
#pragma unroll
        for (int i = 0; i < 32; i += 8)
            t[ty + i][tx] = U[(size_t)(a0 + ty + i) * 65536 + c * 256 + d0 + tx];
        __syncthreads();
#pragma unroll
        for (int i = 0; i < 32; i += 8) {
            int dl = ty + i;
            size_t rowbase = ((size_t)(d0 + dl) * 256 + c) * 256;
            Upt[rowbase + a0 + tx] = __float2half(t[tx][dl]);
        }
    } else {
        const int br = zz - 768;
        const float* W = Ws.p[br];
        f16* Wpt = Wp + (size_t)br * PBW;
        for (int t2i = 0; t2i < 2; t2i++) {
            int tile = ((blockIdx.y * 8 + blockIdx.x) * 2 + t2i);
            int k0 = (tile >> 3) * 32;
            int n0 = (tile & 7) * 32;
            __syncthreads();
#pragma unroll
            for (int i = 0; i < 32; i += 8)
                t[ty + i][tx] = W[(size_t)(k0 + ty + i) * 256 + n0 + tx];
            __syncthreads();
#pragma unroll
            for (int i = 0; i < 32; i += 8) {
                int dl = ty + i;
                float v = t[tx][dl];
                f16 hb = __float2half(v);
                f16 lb = __float2half(v - __half2float(hb));
                size_t rowbase = (size_t)(n0 + dl) * 1024;
                Wpt[rowbase + k0 + tx] = hb;
                Wpt[rowbase + 512 + k0 + tx] = lb;
            }
        }
    }
}

__global__ void build_h16(const float* __restrict__ x, const float* __restrict__ sent,
                          f16* __restrict__ h16)
{
    int idx = blockIdx.x * blockDim.x + threadIdx.x;   // 1024*512
    int rowi = idx >> 9;
    int e = idx & 511;
    int t = rowi & 127;
    int b = rowi >> 7;
    float v = (t == 0) ? sent[e] : x[((size_t)(b * 127 + t - 1)) * 512 + e];
    f16 hb = __float2half(v);
    f16 lb = __float2half(v - __half2float(hb));
    h16[(size_t)rowi * 1024 + e] = hb;
    h16[(size_t)rowi * 1024 + 512 + e] = lb;
}

__global__ void write_mask(const int* __restrict__ mask, float* __restrict__ outm)
{
    int i = blockIdx.x * blockDim.x + threadIdx.x;
    if (i < 1024) {
        int b = i >> 7, t = i & 127;
        outm[i] = (t == 0) ? 1.0f : (float)mask[b * 127 + t - 1];
    }
}

// ===========================================================================
extern "C" void kernel_launch(void* const* d_in, const int* in_sizes, int n_in,
                              void* d_out, int out_size)
{
    (void)in_sizes; (void)n_in; (void)out_size;

    const float* x    = (const float*)d_in[0];
    const int*   mask = (const int*)d_in[2];
    const float* sent = (const float*)d_in[20];
    float* out = (float*)d_out;

    f16 *h16, *Wpb, *projb, *Up, *t1, *t2;
    cudaGetSymbolAddress((void**)&h16,   g_h16);
    cudaGetSymbolAddress((void**)&Wpb,   g_Wp);
    cudaGetSymbolAddress((void**)&projb, g_projb);
    cudaGetSymbolAddress((void**)&Up,    g_Up);
    cudaGetSymbolAddress((void**)&t1,    g_t1);
    cudaGetSymbolAddress((void**)&t2,    g_t2);

    const int SMEM  = 65536 + 3 * 16384 + 1024;   // 115712 -> 2 CTAs/SM (226KB)
    const int SMEMP = 2 * 32768 + 1024;           // 66560  -> 2 CTAs/SM
    cudaFuncSetAttribute(stage1_k, cudaFuncAttributeMaxDynamicSharedMemorySize, SMEM);
    cudaFuncSetAttribute(stage2_k, cudaFuncAttributeMaxDynamicSharedMemorySize, SMEM);
    cudaFuncSetAttribute(stage3_k, cudaFuncAttributeMaxDynamicSharedMemorySize, SMEM);
    cudaFuncSetAttribute(proj_mma, cudaFuncAttributeMaxDynamicSharedMemorySize, SMEMP);

    BiasArgs ba;
    PtrW ws;
    for (int i = 0; i < 7; i++) {
        ws.p[i] = (const float*)d_in[3 + 2 * i];
        ba.b[i] = (const float*)d_in[4 + 2 * i];
    }
    PtrU us;
    us.p[0] = (const float*)d_in[17];
    us.p[1] = (const float*)d_in[18];
    us.p[2] = (const float*)d_in[19];

    // branches: 0 sib_head, 1 sib_dep, 2 cop_head, 3 cop_dep,
    //           4 gp_head, 5 gp_dep, 6 gp_head_dep
    Ptr3 vp = {{ projb + 1 * PB, projb + 3 * PB, projb + 6 * PB }};
    Ptr3 wp = {{ projb + 1 * PB, projb + 2 * PB, projb + 5 * PB }};

    build_h16<<<2048, 256>>>(x, sent, h16);                          // 0
    prep_k<<<dim3(8, 8, 775), dim3(32, 8)>>>(us, Up, ws, Wpb);       // 1
    proj_mma<<<dim3(8, 2, 7), 256, SMEMP>>>(ba, h16, Wpb, projb);    // 2
    stage1_k<<<dim3(8, 64, 3), 128, SMEM>>>(projb, Up, t1);          // 3 <- ncu
    stage2_k<<<dim3(512, 3), 128, SMEM>>>(vp, t1, t2);               // 4
    stage3_k<<<dim3(512, 3), 128, SMEM>>>(wp, t2, out);              // 5
    write_mask<<<4, 256>>>(mask, out + (size_t)3 * 16777216);        // 6
}